// round 16
// baseline (speedup 1.0000x reference)
#include <cuda_runtime.h>
#include <math.h>
#include <float.h>
#include <stdint.h>

#define D        512
#define NTYPES   26
#define NPER     128
#define NCODES   (NTYPES * NPER)
#define MAXN     32768
#define MAXS     1024
#define TEMP     0.07f
#define EPSN     1e-12f
#define MAXTILES 16
#define HB       256
#define WROW     12             // smem words per row: 8 data + 4 pad (conflict-free)
#define STW      (128 * WROW)   // words per K16 sub-array
#define MARGIN   6e-3f
#define JCHUNKS  16

// ---------------- scratch ----------------
__device__ float    g_se[(size_t)MAXS * D];
__device__ float    g_esq[NCODES];
__device__ uint32_t g_ehi[(size_t)NCODES * 256];   // packed bf16 hi, [code][word]
__device__ int      g_hist[HB][NTYPES];
__device__ int      g_off[NTYPES + 1];
__device__ int      g_order[MAXN];
__device__ float    g_sum[MAXS];
__device__ float    g_pos[MAXS];
__device__ float    g_loss;
__device__ int      g_done;

// ---------------- helpers ----------------
__device__ __forceinline__ uint32_t bfpack(float lo, float hi) {
    uint32_t r;
    asm("cvt.rn.bf16x2.f32 %0, %1, %2;" : "=r"(r) : "f"(hi), "f"(lo));
    return r;
}

__device__ __forceinline__ void mma_bf16(float* c, const uint32_t* a, const uint32_t* b) {
    asm volatile(
        "mma.sync.aligned.m16n8k16.row.col.f32.bf16.bf16.f32 "
        "{%0,%1,%2,%3}, {%4,%5,%6,%7}, {%8,%9}, {%0,%1,%2,%3};"
        : "+f"(c[0]), "+f"(c[1]), "+f"(c[2]), "+f"(c[3])
        : "r"(a[0]), "r"(a[1]), "r"(a[2]), "r"(a[3]),
          "r"(b[0]), "r"(b[1]));
}

__device__ __forceinline__ void ldm_x4(uint32_t* r, uint32_t saddr) {
    asm volatile("ldmatrix.sync.aligned.m8n8.x4.shared.b16 {%0,%1,%2,%3}, [%4];"
                 : "=r"(r[0]), "=r"(r[1]), "=r"(r[2]), "=r"(r[3]) : "r"(saddr));
}

__device__ __forceinline__ void cp16(uint32_t dst, const void* src) {
    asm volatile("cp.async.cg.shared.global [%0], [%1], 16;"
                 :: "r"(dst), "l"(src) : "memory");
}
#define CP_COMMIT() asm volatile("cp.async.commit_group;" ::: "memory")
#define CP_WAIT0()  asm volatile("cp.async.wait_group 0;" ::: "memory")

// ---------------- prep: init + esq + E bf16 hi + histogram + se-normalize -----
__global__ __launch_bounds__(128) void k_prep(const float* __restrict__ emb,
                                              const int* __restrict__ Q, int N,
                                              const int* __restrict__ sampled, int S) {
    int b = blockIdx.x;
    if (b < NCODES) {
        if (b == 0 && threadIdx.x == 0) { g_loss = 0.f; }
        const float4* er = (const float4*)(emb + (size_t)b * D);
        float4 a = er[threadIdx.x];
        uint32_t h0 = bfpack(a.x, a.y);
        uint32_t h1 = bfpack(a.z, a.w);
        size_t base = (size_t)b * 256 + threadIdx.x * 2;
        *(uint2*)&g_ehi[base] = make_uint2(h0, h1);
        float ss = a.x*a.x + a.y*a.y + a.z*a.z + a.w*a.w;
        #pragma unroll
        for (int o = 16; o > 0; o >>= 1) ss += __shfl_down_sync(0xffffffffu, ss, o);
        __shared__ float ws[4];
        if ((threadIdx.x & 31) == 0) ws[threadIdx.x >> 5] = ss;
        __syncthreads();
        if (threadIdx.x == 0) g_esq[b] = ws[0] + ws[1] + ws[2] + ws[3];
    } else if (b < NCODES + HB) {
        int h = b - NCODES;
        __shared__ int cnt[NTYPES];
        if (threadIdx.x < NTYPES) cnt[threadIdx.x] = 0;
        __syncthreads();
        int i = h * 128 + threadIdx.x;
        if (i < N) atomicAdd(&cnt[Q[i]], 1);
        __syncthreads();
        if (threadIdx.x < NTYPES) g_hist[h][threadIdx.x] = cnt[threadIdx.x];
    } else {
        int s = b - NCODES - HB;
        int row = sampled[s];
        if (threadIdx.x == 0) { g_sum[s] = 0.f; g_pos[s] = 0.f; }
        float4 a = ((const float4*)(emb + (size_t)row * D))[threadIdx.x];
        float ss = a.x*a.x + a.y*a.y + a.z*a.z + a.w*a.w;
        #pragma unroll
        for (int o = 16; o > 0; o >>= 1) ss += __shfl_down_sync(0xffffffffu, ss, o);
        __shared__ float ws2[4];
        if ((threadIdx.x & 31) == 0) ws2[threadIdx.x >> 5] = ss;
        __syncthreads();
        float tot = ws2[0] + ws2[1] + ws2[2] + ws2[3];
        float inv = 1.0f / fmaxf(sqrtf(tot), EPSN);
        ((float4*)(g_se + (size_t)s * D))[threadIdx.x] =
            make_float4(a.x*inv, a.y*inv, a.z*inv, a.w*inv);
    }
}

// ---------------- scatter (deterministic; block 0 publishes g_off) ------------
__global__ __launch_bounds__(256) void k_scatter(const int* __restrict__ Q, int N) {
    __shared__ int stot[NTYPES], spre[NTYPES], soff[NTYPES + 1], sbase[NTYPES];
    __shared__ int wcnt[8][NTYPES];
    int b = blockIdx.x;
    int tid = threadIdx.x;
    int lane = tid & 31, wid = tid >> 5;

    if (tid < NTYPES) {
        int tot = 0, pre = 0, lim = 2 * b;
        #pragma unroll 8
        for (int r = 0; r < HB; r++) {
            int v = g_hist[r][tid];
            tot += v;
            if (r < lim) pre += v;
        }
        stot[tid] = tot; spre[tid] = pre;
    }
    if (tid < 8 * NTYPES) wcnt[tid / NTYPES][tid % NTYPES] = 0;
    __syncthreads();
    if (tid == 0) {
        int acc = 0;
        #pragma unroll
        for (int t = 0; t < NTYPES; t++) { soff[t] = acc; acc += stot[t]; }
        soff[NTYPES] = acc;
    }
    __syncthreads();
    if (tid < NTYPES) sbase[tid] = soff[tid] + spre[tid];
    if (b == 0 && tid < NTYPES + 1) g_off[tid] = soff[tid];

    int i = b * 256 + tid;
    int ty = (i < N) ? Q[i] : -1;
    unsigned mask = __match_any_sync(0xffffffffu, ty);
    int rinw = __popc(mask & ((1u << lane) - 1u));
    int lead = __ffs(mask) - 1;
    if (lane == lead && ty >= 0) wcnt[wid][ty] = __popc(mask);
    __syncthreads();
    if (ty >= 0) {
        int rank = rinw;
        #pragma unroll
        for (int w = 0; w < 8; w++) if (w < wid) rank += wcnt[w][ty];
        g_order[sbase[ty] + rank] = i;
    }
}

// ---------------- fused (1-D grid, interleaved roles): GEMM + usim + finalize -
extern __shared__ uint32_t dynsm[];
__global__ __launch_bounds__(256, 2) void k_fused(const float* __restrict__ x,
                                                  const float* __restrict__ emb,
                                                  float* __restrict__ out,
                                                  float* __restrict__ out_idx,
                                                  const int* __restrict__ sampled,
                                                  int S, int N, int ngemm) {
    __shared__ float wred[8];
    __shared__ int   sdone;

    int tid = threadIdx.x, lane = tid & 31, wid = tid >> 5;

    // even-interleave role assignment over the 1-D grid
    int total = (int)gridDim.x;
    int bi = (int)blockIdx.x;
    int gcur = (int)(((long long)bi * ngemm) / total);
    int gnxt = (int)(((long long)(bi + 1) * ngemm) / total);
    bool is_gemm = (gnxt > gcur);

    if (is_gemm) {
        // ================= GEMM path =================
        int gemm_id = gcur;
        int t = gemm_id >> 4;          // /MAXTILES
        int tileb = gemm_id & 15;      // %MAXTILES

        __shared__ int   toks[128];
        __shared__ float sEsq[128];
        __shared__ float sRow[128][2];
        __shared__ float sInv[128], sN2[128];
        __shared__ float sval[2][128];
        __shared__ int   sidx[2][128];
        __shared__ int   scol[128];
        __shared__ float sSc[128];
        __shared__ int   cand_cnt[128];
        __shared__ int   cand_col[128][7];
        __shared__ float lsum[4];

        int start = g_off[t], end = g_off[t + 1];
        int tile0 = start + tileb * 128;
        if (tile0 < end) {
            int rows = min(128, end - tile0);

            int g = lane >> 2, tig = lane & 3;
            int m0 = (wid & 3) * 32;
            int nw = wid >> 2;
            int n0 = nw * 64;

            if (tid < 128) {
                toks[tid] = g_order[tile0 + min(tid, rows - 1)];
                sEsq[tid] = g_esq[t * NPER + tid];
            }
            __syncthreads();

            int lm = tid >> 1, half = tid & 1;
            const float4* xr = (const float4*)(x + (size_t)toks[lm] * D);
            const uint32_t* erow = g_ehi + (size_t)(t * NPER + lm) * 256;

            uint32_t smb = (uint32_t)__cvta_generic_to_shared(dynsm);
            uint32_t soby = (uint32_t)((lm * WROW + half * 4) * 4);

            int arow = m0 + (lane & 8) + (lane & 7);
            uint32_t aoff = (uint32_t)((arow * WROW + ((lane & 16) >> 2)) * 4);
            int brow = n0 + ((lane >> 4) & 1) * 8 + (lane & 7);
            uint32_t boff = (uint32_t)((brow * WROW + ((lane >> 3) & 1) * 4) * 4);

            float acc[2][8][4];
            #pragma unroll
            for (int s = 0; s < 2; s++)
                #pragma unroll
                for (int j = 0; j < 8; j++)
                    #pragma unroll
                    for (int c = 0; c < 4; c++) acc[s][j][c] = 0.f;
            float rowsq = 0.f;

            float4 px0, px1, px2, px3;

            #define STORE_X(b)                                                      \
            do {                                                                    \
                uint32_t w0 = bfpack(px0.x, px0.y), w1 = bfpack(px0.z, px0.w);      \
                uint32_t w2 = bfpack(px1.x, px1.y), w3 = bfpack(px1.z, px1.w);      \
                uint32_t w4 = bfpack(px2.x, px2.y), w5 = bfpack(px2.z, px2.w);      \
                uint32_t w6 = bfpack(px3.x, px3.y), w7 = bfpack(px3.z, px3.w);      \
                rowsq += px0.x*px0.x + px0.y*px0.y + px0.z*px0.z + px0.w*px0.w      \
                       + px1.x*px1.x + px1.y*px1.y + px1.z*px1.z + px1.w*px1.w      \
                       + px2.x*px2.x + px2.y*px2.y + px2.z*px2.z + px2.w*px2.w      \
                       + px3.x*px3.x + px3.y*px3.y + px3.z*px3.z + px3.w*px3.w;     \
                *(uint4*)((char*)dynsm + ((b)*2 + 0) * (STW*4) + soby)              \
                    = make_uint4(w0, w1, w2, w3);                                   \
                *(uint4*)((char*)dynsm + ((b)*2 + 1) * (STW*4) + soby)              \
                    = make_uint4(w4, w5, w6, w7);                                   \
            } while (0)

            #define LOAD_X(s)                                                       \
            do {                                                                    \
                px0 = xr[(s)*8 + half*2];     px1 = xr[(s)*8 + half*2 + 1];         \
                px2 = xr[(s)*8 + 4 + half*2]; px3 = xr[(s)*8 + 4 + half*2 + 1];     \
            } while (0)

            #define ISSUE_E(b, s)                                                   \
            do {                                                                    \
                cp16(smb + (uint32_t)(4 + (b)*2 + 0) * (STW*4) + soby,              \
                     erow + (s)*16 + half*4);                                       \
                cp16(smb + (uint32_t)(4 + (b)*2 + 1) * (STW*4) + soby,              \
                     erow + (s)*16 + 8 + half*4);                                   \
                CP_COMMIT();                                                        \
            } while (0)

            LOAD_X(0);
            STORE_X(0);
            ISSUE_E(0, 0);
            LOAD_X(1);

            for (int s = 0; s < 16; s++) {
                int b = s & 1;
                CP_WAIT0();
                __syncthreads();
                if (s < 15) {
                    STORE_X(b ^ 1);
                    ISSUE_E(b ^ 1, s + 1);
                    if (s < 14) LOAD_X(s + 2);
                }
                #pragma unroll
                for (int sub = 0; sub < 2; sub++) {
                    uint32_t baseA = smb + (uint32_t)(b*2 + sub) * (STW*4);
                    uint32_t baseE = smb + (uint32_t)(4 + b*2 + sub) * (STW*4);
                    uint32_t aH[2][4];
                    ldm_x4(aH[0], baseA + aoff);
                    ldm_x4(aH[1], baseA + aoff + 16 * WROW * 4);
                    #pragma unroll
                    for (int jj = 0; jj < 4; jj++) {
                        uint32_t bh[4];
                        ldm_x4(bh, baseE + boff + jj * (16 * WROW * 4));
                        #pragma unroll
                        for (int jh = 0; jh < 2; jh++) {
                            int j = jj * 2 + jh;
                            uint32_t bH[2] = { bh[2*jh], bh[2*jh+1] };
                            mma_bf16(acc[0][j], aH[0], bH);
                            mma_bf16(acc[1][j], aH[1], bH);
                        }
                    }
                }
                __syncthreads();
            }

            sRow[lm][half] = rowsq;
            __syncthreads();
            if (tid < 128) {
                float n2 = sRow[tid][0] + sRow[tid][1];
                sN2[tid]  = n2;
                sInv[tid] = 1.0f / fmaxf(sqrtf(n2), EPSN);
            }
            __syncthreads();

            #pragma unroll
            for (int s = 0; s < 2; s++) {
                #pragma unroll
                for (int rh = 0; rh < 2; rh++) {
                    int row = m0 + s*16 + g + rh*8;
                    float inv2 = 2.0f * sInv[row];
                    float bv = FLT_MAX;
                    int   bi2 = 1 << 30;
                    #pragma unroll
                    for (int j = 0; j < 8; j++) {
                        #pragma unroll
                        for (int cc = 0; cc < 2; cc++) {
                            int col = n0 + 8*j + 2*tig + cc;
                            float sc = fmaf(-inv2, acc[s][j][rh*2 + cc], sEsq[col]);
                            if (sc < bv || (sc == bv && col < bi2)) { bv = sc; bi2 = col; }
                        }
                    }
                    #pragma unroll
                    for (int o = 2; o > 0; o >>= 1) {
                        float ov = __shfl_down_sync(0xffffffffu, bv, o, 4);
                        int   oi = __shfl_down_sync(0xffffffffu, bi2, o, 4);
                        if (ov < bv || (ov == bv && oi < bi2)) { bv = ov; bi2 = oi; }
                    }
                    if (tig == 0) { sval[nw][row] = bv; sidx[nw][row] = bi2; }
                }
            }
            __syncthreads();

            if (tid < 128) {
                cand_cnt[tid] = 0;
                float v0 = sval[0][tid], v1 = sval[1][tid];
                int   i0 = sidx[0][tid], i1 = sidx[1][tid];
                if (v1 < v0 || (v1 == v0 && i1 < i0)) { scol[tid] = i1; sSc[tid] = v1; }
                else                                  { scol[tid] = i0; sSc[tid] = v0; }
            }
            __syncthreads();

            #pragma unroll
            for (int s = 0; s < 2; s++) {
                #pragma unroll
                for (int rh = 0; rh < 2; rh++) {
                    int row = m0 + s*16 + g + rh*8;
                    float inv2 = 2.0f * sInv[row];
                    float thresh = sSc[row] + MARGIN;
                    int   win = scol[row];
                    #pragma unroll
                    for (int j = 0; j < 8; j++) {
                        #pragma unroll
                        for (int cc = 0; cc < 2; cc++) {
                            int col = n0 + 8*j + 2*tig + cc;
                            float sc = fmaf(-inv2, acc[s][j][rh*2 + cc], sEsq[col]);
                            if (sc <= thresh && col != win) {
                                int p = atomicAdd(&cand_cnt[row], 1);
                                if (p < 7) cand_col[row][p] = col;
                            }
                        }
                    }
                }
            }
            __syncthreads();

            const float* ebase = emb + (size_t)t * NPER * D;
            for (int r = wid; r < rows; r += 8) {
                int nc = cand_cnt[r];
                if (nc == 0) continue;
                int tok = toks[r];
                const float4* xp = (const float4*)(x + (size_t)tok * D);
                float4 xa = xp[lane], xb = xp[lane + 32],
                       xc = xp[lane + 64], xd = xp[lane + 96];
                float inv2 = 2.0f * sInv[r];
                float bv = FLT_MAX;
                int   bi2 = 1 << 30;
                int total2 = (nc > 7) ? NPER : (nc + 1);
                for (int q = 0; q < total2; q++) {
                    int col;
                    if (nc > 7) col = q;
                    else        col = (q == 0) ? scol[r] : cand_col[r][q - 1];
                    const float4* ep = (const float4*)(ebase + (size_t)col * D);
                    float4 ea = ep[lane], eb = ep[lane + 32],
                           ec = ep[lane + 64], ed = ep[lane + 96];
                    float d = xa.x*ea.x + xa.y*ea.y + xa.z*ea.z + xa.w*ea.w
                            + xb.x*eb.x + xb.y*eb.y + xb.z*eb.z + xb.w*eb.w
                            + xc.x*ec.x + xc.y*ec.y + xc.z*ec.z + xc.w*ec.w
                            + xd.x*ed.x + xd.y*ed.y + xd.z*ed.z + xd.w*ed.w;
                    #pragma unroll
                    for (int o = 16; o > 0; o >>= 1)
                        d += __shfl_xor_sync(0xffffffffu, d, o);
                    float sc = fmaf(-inv2, d, sEsq[col]);
                    if (sc < bv || (sc == bv && col < bi2)) { bv = sc; bi2 = col; }
                }
                if (lane == 0) { scol[r] = bi2; sSc[r] = bv; }
            }
            __syncthreads();

            float lacc = 0.f;
            if (tid < 128 && tid < rows) {
                int col = scol[tid];
                out_idx[toks[tid]] = (float)(t * NPER + col);
                float esqw = sEsq[col];
                float inve = 1.0f / fmaxf(sqrtf(esqw), EPSN);
                lacc = esqw*inve*inve + sN2[tid]*sInv[tid]*sInv[tid]
                     - (esqw - sSc[tid])*inve;
            }
            #pragma unroll
            for (int o = 16; o > 0; o >>= 1)
                lacc += __shfl_down_sync(0xffffffffu, lacc, o);
            if (tid < 128 && lane == 0) lsum[wid] = lacc;
            __syncthreads();
            if (tid == 0)
                atomicAdd(&g_loss, lsum[0] + lsum[1] + lsum[2] + lsum[3]);

            for (int r = wid; r < rows; r += 8) {
                int tok = toks[r];
                int col = scol[r];
                float inve = 1.0f / fmaxf(sqrtf(sEsq[col]), EPSN);
                const float4* ep = (const float4*)(ebase + (size_t)col * D);
                float4* op = (float4*)(out + (size_t)tok * D);
                #pragma unroll
                for (int q = 0; q < 4; q++) {
                    float4 e = ep[lane + q*32];
                    op[lane + q*32] =
                        make_float4(e.x*inve, e.y*inve, e.z*inve, e.w*inve);
                }
            }
        }
    } else {
        // ================= usim path =================
        int usim_id = bi - gnxt;       // 0..nusim-1 in dispatch order
        int jc   = usim_id & 15;       // j-chunk
        int yrow = usim_id >> 4;       // i-row group

        __shared__ int jlab[8];
        float (*sj)[D] = (float(*)[D])dynsm;

        int i = yrow * 8 + wid;
        int jlen = (S + JCHUNKS - 1) / JCHUNKS;
        int j0 = jc * jlen;
        int jend = min(S, j0 + jlen);

        bool active = (i < S);
        int labi = active ? (sampled[i] / NPER) : -1;
        float4 xi0, xi1, xi2, xi3;
        if (active) {
            const float4* ip = (const float4*)(g_se + (size_t)i * D);
            xi0 = ip[lane]; xi1 = ip[lane + 32];
            xi2 = ip[lane + 64]; xi3 = ip[lane + 96];
        }
        float sum = 0.f, pos = 0.f;

        for (int jt = j0; jt < jend; jt += 8) {
            int nr = min(8, jend - jt);
            __syncthreads();
            int r = tid >> 5;
            if (r < nr) {
                const float4* jp = (const float4*)(g_se + (size_t)(jt + r) * D);
                float4* dp = (float4*)sj[r];
                dp[lane] = jp[lane]; dp[lane + 32] = jp[lane + 32];
                dp[lane + 64] = jp[lane + 64]; dp[lane + 96] = jp[lane + 96];
            }
            if (tid < nr) jlab[tid] = sampled[jt + tid] / NPER;
            __syncthreads();
            if (active) {
                int rr = 0;
                for (; rr + 1 < nr; rr += 2) {
                    const float4* b0p = (const float4*)sj[rr];
                    const float4* b1p = (const float4*)sj[rr + 1];
                    float4 a0 = b0p[lane], a1 = b0p[lane + 32],
                           a2 = b0p[lane + 64], a3 = b0p[lane + 96];
                    float4 c0 = b1p[lane], c1 = b1p[lane + 32],
                           c2 = b1p[lane + 64], c3 = b1p[lane + 96];
                    float d0 = xi0.x*a0.x + xi0.y*a0.y + xi0.z*a0.z + xi0.w*a0.w
                             + xi1.x*a1.x + xi1.y*a1.y + xi1.z*a1.z + xi1.w*a1.w
                             + xi2.x*a2.x + xi2.y*a2.y + xi2.z*a2.z + xi2.w*a2.w
                             + xi3.x*a3.x + xi3.y*a3.y + xi3.z*a3.z + xi3.w*a3.w;
                    float d1 = xi0.x*c0.x + xi0.y*c0.y + xi0.z*c0.z + xi0.w*c0.w
                             + xi1.x*c1.x + xi1.y*c1.y + xi1.z*c1.z + xi1.w*c1.w
                             + xi2.x*c2.x + xi2.y*c2.y + xi2.z*c2.z + xi2.w*c2.w
                             + xi3.x*c3.x + xi3.y*c3.y + xi3.z*c3.z + xi3.w*c3.w;
                    #pragma unroll
                    for (int o = 16; o > 0; o >>= 1) {
                        d0 += __shfl_down_sync(0xffffffffu, d0, o);
                        d1 += __shfl_down_sync(0xffffffffu, d1, o);
                    }
                    if (lane == 0) {
                        if (jt + rr != i) {
                            float e = expf(d0 / TEMP);
                            sum += e;
                            if (jlab[rr] == labi) pos += e;
                        }
                        if (jt + rr + 1 != i) {
                            float e = expf(d1 / TEMP);
                            sum += e;
                            if (jlab[rr + 1] == labi) pos += e;
                        }
                    }
                }
                if (rr < nr) {
                    const float4* bp = (const float4*)sj[rr];
                    float4 b0 = bp[lane], b1 = bp[lane + 32],
                           b2 = bp[lane + 64], b3 = bp[lane + 96];
                    float d = xi0.x*b0.x + xi0.y*b0.y + xi0.z*b0.z + xi0.w*b0.w
                            + xi1.x*b1.x + xi1.y*b1.y + xi1.z*b1.z + xi1.w*b1.w
                            + xi2.x*b2.x + xi2.y*b2.y + xi2.z*b2.z + xi2.w*b2.w
                            + xi3.x*b3.x + xi3.y*b3.y + xi3.z*b3.z + xi3.w*b3.w;
                    #pragma unroll
                    for (int o = 16; o > 0; o >>= 1)
                        d += __shfl_down_sync(0xffffffffu, d, o);
                    if (lane == 0 && (jt + rr) != i) {
                        float e = expf(d / TEMP);
                        sum += e;
                        if (jlab[rr] == labi) pos += e;
                    }
                }
            }
        }
        if (active && lane == 0) {
            atomicAdd(&g_sum[i], sum);
            atomicAdd(&g_pos[i], pos);
        }
    }

    // ================= arrive + finalize (all blocks) =================
    __threadfence();
    __syncthreads();
    if (tid == 0) {
        int old = atomicAdd(&g_done, 1);
        sdone = (old == (int)gridDim.x - 1) ? 1 : 0;
    }
    __syncthreads();
    if (sdone) {
        float l = 0.f;
        for (int q = tid; q < S; q += 256)
            l += -logf(g_pos[q] / g_sum[q]);
        #pragma unroll
        for (int o = 16; o > 0; o >>= 1) l += __shfl_down_sync(0xffffffffu, l, o);
        if (lane == 0) wred[wid] = l;
        __syncthreads();
        if (tid == 0) {
            float usum = 0.f;
            #pragma unroll
            for (int w = 0; w < 8; w++) usum += wred[w];
            size_t ND = (size_t)N * D;
            out[ND]     = 1.25f * g_loss / (float)((size_t)N * D);
            out[ND + 1] = usum / (float)S;
            g_done = 0;
        }
    }
}

// ---------------- launcher ----------------
extern "C" void kernel_launch(void* const* d_in, const int* in_sizes, int n_in,
                              void* d_out, int out_size) {
    const float* x       = (const float*)d_in[0];
    const int*   Q       = (const int*)d_in[1];
    const float* emb     = (const float*)d_in[2];
    const int*   sampled = (const int*)d_in[3];
    float* out = (float*)d_out;

    int N = in_sizes[0] / D;
    int S = in_sizes[3];
    size_t ND = (size_t)N * D;
    float* out_idx = out + ND + 2;

    cudaFuncSetAttribute(k_fused, cudaFuncAttributeMaxDynamicSharedMemorySize,
                         8 * STW * 4);

    k_prep<<<NCODES + HB + S, 128>>>(emb, Q, N, sampled, S);
    k_scatter<<<(N + 255) / 256, 256>>>(Q, N);
    int ngemm = MAXTILES * NTYPES;
    int nusim = MAXTILES * ((S + 7) / 8);
    int total = ngemm + nusim;
    k_fused<<<total, 256, 8 * STW * 4>>>(x, emb, out, out_idx, sampled, S, N, ngemm);
}

// round 17
// speedup vs baseline: 1.4379x; 1.4379x over previous
#include <cuda_runtime.h>
#include <math.h>
#include <float.h>
#include <stdint.h>

#define D        512
#define NTYPES   26
#define NPER     128
#define NCODES   (NTYPES * NPER)
#define MAXN     32768
#define MAXS     1024
#define TEMP     0.07f
#define EPSN     1e-12f
#define MAXTILES 16
#define HB       256
#define WROW     12             // smem words per row: 8 data + 4 pad (conflict-free)
#define STW      (128 * WROW)   // words per K16 sub-array
#define MARGIN   6e-3f
#define JCHUNKS  16             // == MAXTILES (usim j-chunks ride blockIdx.x)

// ---------------- scratch ----------------
__device__ float    g_se[(size_t)MAXS * D];
__device__ float    g_esq[NCODES];
__device__ uint32_t g_ehi[(size_t)NCODES * 256];   // packed bf16 hi, [code][word]
__device__ int      g_hist[HB][NTYPES];
__device__ int      g_off[NTYPES + 1];
__device__ int      g_order[MAXN];
__device__ float    g_sum[MAXS];
__device__ float    g_pos[MAXS];
__device__ float    g_loss;
__device__ int      g_done;

// ---------------- helpers ----------------
__device__ __forceinline__ uint32_t bfpack(float lo, float hi) {
    uint32_t r;
    asm("cvt.rn.bf16x2.f32 %0, %1, %2;" : "=r"(r) : "f"(hi), "f"(lo));
    return r;
}

__device__ __forceinline__ void mma_bf16(float* c, const uint32_t* a, const uint32_t* b) {
    asm volatile(
        "mma.sync.aligned.m16n8k16.row.col.f32.bf16.bf16.f32 "
        "{%0,%1,%2,%3}, {%4,%5,%6,%7}, {%8,%9}, {%0,%1,%2,%3};"
        : "+f"(c[0]), "+f"(c[1]), "+f"(c[2]), "+f"(c[3])
        : "r"(a[0]), "r"(a[1]), "r"(a[2]), "r"(a[3]),
          "r"(b[0]), "r"(b[1]));
}

__device__ __forceinline__ void ldm_x4(uint32_t* r, uint32_t saddr) {
    asm volatile("ldmatrix.sync.aligned.m8n8.x4.shared.b16 {%0,%1,%2,%3}, [%4];"
                 : "=r"(r[0]), "=r"(r[1]), "=r"(r[2]), "=r"(r[3]) : "r"(saddr));
}

__device__ __forceinline__ void cp16(uint32_t dst, const void* src) {
    asm volatile("cp.async.cg.shared.global [%0], [%1], 16;"
                 :: "r"(dst), "l"(src) : "memory");
}
#define CP_COMMIT() asm volatile("cp.async.commit_group;" ::: "memory")
#define CP_WAIT0()  asm volatile("cp.async.wait_group 0;" ::: "memory")

// ---------------- prep: init + esq + E bf16 hi + histogram + se-normalize -----
__global__ __launch_bounds__(128) void k_prep(const float* __restrict__ emb,
                                              const int* __restrict__ Q, int N,
                                              const int* __restrict__ sampled, int S) {
    int b = blockIdx.x;
    if (b < NCODES) {
        if (b == 0 && threadIdx.x == 0) { g_loss = 0.f; }
        const float4* er = (const float4*)(emb + (size_t)b * D);
        float4 a = er[threadIdx.x];
        uint32_t h0 = bfpack(a.x, a.y);
        uint32_t h1 = bfpack(a.z, a.w);
        size_t base = (size_t)b * 256 + threadIdx.x * 2;
        *(uint2*)&g_ehi[base] = make_uint2(h0, h1);
        float ss = a.x*a.x + a.y*a.y + a.z*a.z + a.w*a.w;
        #pragma unroll
        for (int o = 16; o > 0; o >>= 1) ss += __shfl_down_sync(0xffffffffu, ss, o);
        __shared__ float ws[4];
        if ((threadIdx.x & 31) == 0) ws[threadIdx.x >> 5] = ss;
        __syncthreads();
        if (threadIdx.x == 0) g_esq[b] = ws[0] + ws[1] + ws[2] + ws[3];
    } else if (b < NCODES + HB) {
        int h = b - NCODES;
        __shared__ int cnt[NTYPES];
        if (threadIdx.x < NTYPES) cnt[threadIdx.x] = 0;
        __syncthreads();
        int i = h * 128 + threadIdx.x;
        if (i < N) atomicAdd(&cnt[Q[i]], 1);
        __syncthreads();
        if (threadIdx.x < NTYPES) g_hist[h][threadIdx.x] = cnt[threadIdx.x];
    } else {
        int s = b - NCODES - HB;
        int row = sampled[s];
        if (threadIdx.x == 0) { g_sum[s] = 0.f; g_pos[s] = 0.f; }
        float4 a = ((const float4*)(emb + (size_t)row * D))[threadIdx.x];
        float ss = a.x*a.x + a.y*a.y + a.z*a.z + a.w*a.w;
        #pragma unroll
        for (int o = 16; o > 0; o >>= 1) ss += __shfl_down_sync(0xffffffffu, ss, o);
        __shared__ float ws2[4];
        if ((threadIdx.x & 31) == 0) ws2[threadIdx.x >> 5] = ss;
        __syncthreads();
        float tot = ws2[0] + ws2[1] + ws2[2] + ws2[3];
        float inv = 1.0f / fmaxf(sqrtf(tot), EPSN);
        ((float4*)(g_se + (size_t)s * D))[threadIdx.x] =
            make_float4(a.x*inv, a.y*inv, a.z*inv, a.w*inv);
    }
}

// ---------------- scatter (parallel hist-scan; block 0 publishes g_off) -------
__global__ __launch_bounds__(256) void k_scatter(const int* __restrict__ Q, int N) {
    __shared__ int ptot[8][NTYPES], ppre[8][NTYPES];
    __shared__ int stot[NTYPES], soff[NTYPES + 1], sbase[NTYPES];
    __shared__ int wcnt[8][NTYPES];
    int b = blockIdx.x;
    int tid = threadIdx.x;
    int lane = tid & 31, wid = tid >> 5;

    // parallel column sums: 8 chunks x 26 types (208 threads), 32 rows each
    if (tid < 8 * NTYPES) {
        int c = tid / NTYPES, t = tid % NTYPES;
        int lim = 2 * b;
        int tot = 0, pre = 0;
        int r0 = c * 32;
        #pragma unroll 8
        for (int r = r0; r < r0 + 32; r++) {
            int v = g_hist[r][t];
            tot += v;
            if (r < lim) pre += v;
        }
        ptot[c][t] = tot;
        ppre[c][t] = pre;
        wcnt[c][t] = 0;
    }
    __syncthreads();
    if (tid < NTYPES) {
        int tot = 0, pre = 0;
        #pragma unroll
        for (int c = 0; c < 8; c++) { tot += ptot[c][tid]; pre += ppre[c][tid]; }
        stot[tid] = tot;
        ppre[0][tid] = pre;   // reuse as combined prefix
    }
    __syncthreads();
    if (tid == 0) {
        int acc = 0;
        #pragma unroll
        for (int t = 0; t < NTYPES; t++) { soff[t] = acc; acc += stot[t]; }
        soff[NTYPES] = acc;
    }
    __syncthreads();
    if (tid < NTYPES) sbase[tid] = soff[tid] + ppre[0][tid];
    if (b == 0 && tid < NTYPES + 1) g_off[tid] = soff[tid];

    int i = b * 256 + tid;
    int ty = (i < N) ? Q[i] : -1;
    unsigned mask = __match_any_sync(0xffffffffu, ty);
    int rinw = __popc(mask & ((1u << lane) - 1u));
    int lead = __ffs(mask) - 1;
    if (lane == lead && ty >= 0) wcnt[wid][ty] = __popc(mask);
    __syncthreads();
    if (ty >= 0) {
        int rank = rinw;
        #pragma unroll
        for (int w = 0; w < 8; w++) if (w < wid) rank += wcnt[w][ty];
        g_order[sbase[ty] + rank] = i;
    }
}

// ---------------- fused: bf16 GEMM path  +  usim path  +  finalize ------------
extern __shared__ uint32_t dynsm[];
__global__ __launch_bounds__(256, 2) void k_fused(const float* __restrict__ x,
                                                  const float* __restrict__ emb,
                                                  float* __restrict__ out,
                                                  float* __restrict__ out_idx,
                                                  const int* __restrict__ sampled,
                                                  int S, int N) {
    __shared__ float wred[8];
    __shared__ int   sdone;

    int tid = threadIdx.x, lane = tid & 31, wid = tid >> 5;

    if (blockIdx.y < NTYPES) {
        // ================= GEMM path =================
        __shared__ int   toks[128];
        __shared__ float sEsq[128];
        __shared__ float sRow[128][2];
        __shared__ float sInv[128], sN2[128];
        __shared__ float sval[2][128];
        __shared__ int   sidx[2][128];
        __shared__ int   scol[128];
        __shared__ float sSc[128];
        __shared__ int   cand_cnt[128];
        __shared__ int   cand_col[128][7];
        __shared__ float lsum[4];

        int t = blockIdx.y;
        int start = g_off[t], end = g_off[t + 1];
        int tile0 = start + blockIdx.x * 128;
        if (tile0 < end) {
            int rows = min(128, end - tile0);

            int g = lane >> 2, tig = lane & 3;
            int m0 = (wid & 3) * 32;
            int nw = wid >> 2;
            int n0 = nw * 64;

            if (tid < 128) {
                toks[tid] = g_order[tile0 + min(tid, rows - 1)];
                sEsq[tid] = g_esq[t * NPER + tid];
            }
            __syncthreads();

            int lm = tid >> 1, half = tid & 1;
            const float4* xr = (const float4*)(x + (size_t)toks[lm] * D);
            const uint32_t* erow = g_ehi + (size_t)(t * NPER + lm) * 256;

            uint32_t smb = (uint32_t)__cvta_generic_to_shared(dynsm);
            uint32_t soby = (uint32_t)((lm * WROW + half * 4) * 4);

            int arow = m0 + (lane & 8) + (lane & 7);
            uint32_t aoff = (uint32_t)((arow * WROW + ((lane & 16) >> 2)) * 4);
            int brow = n0 + ((lane >> 4) & 1) * 8 + (lane & 7);
            uint32_t boff = (uint32_t)((brow * WROW + ((lane >> 3) & 1) * 4) * 4);

            float acc[2][8][4];
            #pragma unroll
            for (int s = 0; s < 2; s++)
                #pragma unroll
                for (int j = 0; j < 8; j++)
                    #pragma unroll
                    for (int c = 0; c < 4; c++) acc[s][j][c] = 0.f;
            float rowsq = 0.f;

            float4 px0, px1, px2, px3;

            #define STORE_X(b)                                                      \
            do {                                                                    \
                uint32_t w0 = bfpack(px0.x, px0.y), w1 = bfpack(px0.z, px0.w);      \
                uint32_t w2 = bfpack(px1.x, px1.y), w3 = bfpack(px1.z, px1.w);      \
                uint32_t w4 = bfpack(px2.x, px2.y), w5 = bfpack(px2.z, px2.w);      \
                uint32_t w6 = bfpack(px3.x, px3.y), w7 = bfpack(px3.z, px3.w);      \
                rowsq += px0.x*px0.x + px0.y*px0.y + px0.z*px0.z + px0.w*px0.w      \
                       + px1.x*px1.x + px1.y*px1.y + px1.z*px1.z + px1.w*px1.w      \
                       + px2.x*px2.x + px2.y*px2.y + px2.z*px2.z + px2.w*px2.w      \
                       + px3.x*px3.x + px3.y*px3.y + px3.z*px3.z + px3.w*px3.w;     \
                *(uint4*)((char*)dynsm + ((b)*2 + 0) * (STW*4) + soby)              \
                    = make_uint4(w0, w1, w2, w3);                                   \
                *(uint4*)((char*)dynsm + ((b)*2 + 1) * (STW*4) + soby)              \
                    = make_uint4(w4, w5, w6, w7);                                   \
            } while (0)

            #define LOAD_X(s)                                                       \
            do {                                                                    \
                px0 = xr[(s)*8 + half*2];     px1 = xr[(s)*8 + half*2 + 1];         \
                px2 = xr[(s)*8 + 4 + half*2]; px3 = xr[(s)*8 + 4 + half*2 + 1];     \
            } while (0)

            #define ISSUE_E(b, s)                                                   \
            do {                                                                    \
                cp16(smb + (uint32_t)(4 + (b)*2 + 0) * (STW*4) + soby,              \
                     erow + (s)*16 + half*4);                                       \
                cp16(smb + (uint32_t)(4 + (b)*2 + 1) * (STW*4) + soby,              \
                     erow + (s)*16 + 8 + half*4);                                   \
                CP_COMMIT();                                                        \
            } while (0)

            LOAD_X(0);
            STORE_X(0);
            ISSUE_E(0, 0);
            LOAD_X(1);

            for (int s = 0; s < 16; s++) {
                int b = s & 1;
                CP_WAIT0();
                __syncthreads();
                if (s < 15) {
                    STORE_X(b ^ 1);
                    ISSUE_E(b ^ 1, s + 1);
                    if (s < 14) LOAD_X(s + 2);
                }
                #pragma unroll
                for (int sub = 0; sub < 2; sub++) {
                    uint32_t baseA = smb + (uint32_t)(b*2 + sub) * (STW*4);
                    uint32_t baseE = smb + (uint32_t)(4 + b*2 + sub) * (STW*4);
                    uint32_t aH[2][4];
                    ldm_x4(aH[0], baseA + aoff);
                    ldm_x4(aH[1], baseA + aoff + 16 * WROW * 4);
                    #pragma unroll
                    for (int jj = 0; jj < 4; jj++) {
                        uint32_t bh[4];
                        ldm_x4(bh, baseE + boff + jj * (16 * WROW * 4));
                        #pragma unroll
                        for (int jh = 0; jh < 2; jh++) {
                            int j = jj * 2 + jh;
                            uint32_t bH[2] = { bh[2*jh], bh[2*jh+1] };
                            mma_bf16(acc[0][j], aH[0], bH);
                            mma_bf16(acc[1][j], aH[1], bH);
                        }
                    }
                }
                __syncthreads();
            }

            sRow[lm][half] = rowsq;
            __syncthreads();
            if (tid < 128) {
                float n2 = sRow[tid][0] + sRow[tid][1];
                sN2[tid]  = n2;
                sInv[tid] = 1.0f / fmaxf(sqrtf(n2), EPSN);
            }
            __syncthreads();

            #pragma unroll
            for (int s = 0; s < 2; s++) {
                #pragma unroll
                for (int rh = 0; rh < 2; rh++) {
                    int row = m0 + s*16 + g + rh*8;
                    float inv2 = 2.0f * sInv[row];
                    float bv = FLT_MAX;
                    int   bi = 1 << 30;
                    #pragma unroll
                    for (int j = 0; j < 8; j++) {
                        #pragma unroll
                        for (int cc = 0; cc < 2; cc++) {
                            int col = n0 + 8*j + 2*tig + cc;
                            float sc = fmaf(-inv2, acc[s][j][rh*2 + cc], sEsq[col]);
                            if (sc < bv || (sc == bv && col < bi)) { bv = sc; bi = col; }
                        }
                    }
                    #pragma unroll
                    for (int o = 2; o > 0; o >>= 1) {
                        float ov = __shfl_down_sync(0xffffffffu, bv, o, 4);
                        int   oi = __shfl_down_sync(0xffffffffu, bi, o, 4);
                        if (ov < bv || (ov == bv && oi < bi)) { bv = ov; bi = oi; }
                    }
                    if (tig == 0) { sval[nw][row] = bv; sidx[nw][row] = bi; }
                }
            }
            __syncthreads();

            if (tid < 128) {
                cand_cnt[tid] = 0;
                float v0 = sval[0][tid], v1 = sval[1][tid];
                int   i0 = sidx[0][tid], i1 = sidx[1][tid];
                if (v1 < v0 || (v1 == v0 && i1 < i0)) { scol[tid] = i1; sSc[tid] = v1; }
                else                                  { scol[tid] = i0; sSc[tid] = v0; }
            }
            __syncthreads();

            #pragma unroll
            for (int s = 0; s < 2; s++) {
                #pragma unroll
                for (int rh = 0; rh < 2; rh++) {
                    int row = m0 + s*16 + g + rh*8;
                    float inv2 = 2.0f * sInv[row];
                    float thresh = sSc[row] + MARGIN;
                    int   win = scol[row];
                    #pragma unroll
                    for (int j = 0; j < 8; j++) {
                        #pragma unroll
                        for (int cc = 0; cc < 2; cc++) {
                            int col = n0 + 8*j + 2*tig + cc;
                            float sc = fmaf(-inv2, acc[s][j][rh*2 + cc], sEsq[col]);
                            if (sc <= thresh && col != win) {
                                int p = atomicAdd(&cand_cnt[row], 1);
                                if (p < 7) cand_col[row][p] = col;
                            }
                        }
                    }
                }
            }
            __syncthreads();

            const float* ebase = emb + (size_t)t * NPER * D;
            for (int r = wid; r < rows; r += 8) {
                int nc = cand_cnt[r];
                if (nc == 0) continue;
                int tok = toks[r];
                const float4* xp = (const float4*)(x + (size_t)tok * D);
                float4 xa = xp[lane], xb = xp[lane + 32],
                       xc = xp[lane + 64], xd = xp[lane + 96];
                float inv2 = 2.0f * sInv[r];
                float bv = FLT_MAX;
                int   bi = 1 << 30;
                int total = (nc > 7) ? NPER : (nc + 1);
                for (int q = 0; q < total; q++) {
                    int col;
                    if (nc > 7) col = q;
                    else        col = (q == 0) ? scol[r] : cand_col[r][q - 1];
                    const float4* ep = (const float4*)(ebase + (size_t)col * D);
                    float4 ea = ep[lane], eb = ep[lane + 32],
                           ec = ep[lane + 64], ed = ep[lane + 96];
                    float d = xa.x*ea.x + xa.y*ea.y + xa.z*ea.z + xa.w*ea.w
                            + xb.x*eb.x + xb.y*eb.y + xb.z*eb.z + xb.w*eb.w
                            + xc.x*ec.x + xc.y*ec.y + xc.z*ec.z + xc.w*ec.w
                            + xd.x*ed.x + xd.y*ed.y + xd.z*ed.z + xd.w*ed.w;
                    #pragma unroll
                    for (int o = 16; o > 0; o >>= 1)
                        d += __shfl_xor_sync(0xffffffffu, d, o);
                    float sc = fmaf(-inv2, d, sEsq[col]);
                    if (sc < bv || (sc == bv && col < bi)) { bv = sc; bi = col; }
                }
                if (lane == 0) { scol[r] = bi; sSc[r] = bv; }
            }
            __syncthreads();

            float lacc = 0.f;
            if (tid < 128 && tid < rows) {
                int col = scol[tid];
                out_idx[toks[tid]] = (float)(t * NPER + col);
                float esqw = sEsq[col];
                float inve = 1.0f / fmaxf(sqrtf(esqw), EPSN);
                lacc = esqw*inve*inve + sN2[tid]*sInv[tid]*sInv[tid]
                     - (esqw - sSc[tid])*inve;
            }
            #pragma unroll
            for (int o = 16; o > 0; o >>= 1)
                lacc += __shfl_down_sync(0xffffffffu, lacc, o);
            if (tid < 128 && lane == 0) lsum[wid] = lacc;
            __syncthreads();
            if (tid == 0)
                atomicAdd(&g_loss, lsum[0] + lsum[1] + lsum[2] + lsum[3]);

            for (int r = wid; r < rows; r += 8) {
                int tok = toks[r];
                int col = scol[r];
                float inve = 1.0f / fmaxf(sqrtf(sEsq[col]), EPSN);
                const float4* ep = (const float4*)(ebase + (size_t)col * D);
                float4* op = (float4*)(out + (size_t)tok * D);
                #pragma unroll
                for (int q = 0; q < 4; q++) {
                    float4 e = ep[lane + q*32];
                    op[lane + q*32] =
                        make_float4(e.x*inve, e.y*inve, e.z*inve, e.w*inve);
                }
            }
        }
    } else {
        // ================= usim path =================
        __shared__ int jlab[8];
        float (*sj)[D] = (float(*)[D])dynsm;

        int i = (blockIdx.y - NTYPES) * 8 + wid;
        int jlen = (S + JCHUNKS - 1) / JCHUNKS;
        int j0 = blockIdx.x * jlen;
        int jend = min(S, j0 + jlen);

        bool active = (i < S);
        int labi = active ? (sampled[i] / NPER) : -1;
        float4 xi0, xi1, xi2, xi3;
        if (active) {
            const float4* ip = (const float4*)(g_se + (size_t)i * D);
            xi0 = ip[lane]; xi1 = ip[lane + 32];
            xi2 = ip[lane + 64]; xi3 = ip[lane + 96];
        }
        float sum = 0.f, pos = 0.f;

        for (int jt = j0; jt < jend; jt += 8) {
            int nr = min(8, jend - jt);
            __syncthreads();
            int r = tid >> 5;
            if (r < nr) {
                const float4* jp = (const float4*)(g_se + (size_t)(jt + r) * D);
                float4* dp = (float4*)sj[r];
                dp[lane] = jp[lane]; dp[lane + 32] = jp[lane + 32];
                dp[lane + 64] = jp[lane + 64]; dp[lane + 96] = jp[lane + 96];
            }
            if (tid < nr) jlab[tid] = sampled[jt + tid] / NPER;
            __syncthreads();
            if (active) {
                int rr = 0;
                for (; rr + 1 < nr; rr += 2) {
                    const float4* b0p = (const float4*)sj[rr];
                    const float4* b1p = (const float4*)sj[rr + 1];
                    float4 a0 = b0p[lane], a1 = b0p[lane + 32],
                           a2 = b0p[lane + 64], a3 = b0p[lane + 96];
                    float4 c0 = b1p[lane], c1 = b1p[lane + 32],
                           c2 = b1p[lane + 64], c3 = b1p[lane + 96];
                    float d0 = xi0.x*a0.x + xi0.y*a0.y + xi0.z*a0.z + xi0.w*a0.w
                             + xi1.x*a1.x + xi1.y*a1.y + xi1.z*a1.z + xi1.w*a1.w
                             + xi2.x*a2.x + xi2.y*a2.y + xi2.z*a2.z + xi2.w*a2.w
                             + xi3.x*a3.x + xi3.y*a3.y + xi3.z*a3.z + xi3.w*a3.w;
                    float d1 = xi0.x*c0.x + xi0.y*c0.y + xi0.z*c0.z + xi0.w*c0.w
                             + xi1.x*c1.x + xi1.y*c1.y + xi1.z*c1.z + xi1.w*c1.w
                             + xi2.x*c2.x + xi2.y*c2.y + xi2.z*c2.z + xi2.w*c2.w
                             + xi3.x*c3.x + xi3.y*c3.y + xi3.z*c3.z + xi3.w*c3.w;
                    #pragma unroll
                    for (int o = 16; o > 0; o >>= 1) {
                        d0 += __shfl_down_sync(0xffffffffu, d0, o);
                        d1 += __shfl_down_sync(0xffffffffu, d1, o);
                    }
                    if (lane == 0) {
                        if (jt + rr != i) {
                            float e = expf(d0 / TEMP);
                            sum += e;
                            if (jlab[rr] == labi) pos += e;
                        }
                        if (jt + rr + 1 != i) {
                            float e = expf(d1 / TEMP);
                            sum += e;
                            if (jlab[rr + 1] == labi) pos += e;
                        }
                    }
                }
                if (rr < nr) {
                    const float4* bp = (const float4*)sj[rr];
                    float4 b0 = bp[lane], b1 = bp[lane + 32],
                           b2 = bp[lane + 64], b3 = bp[lane + 96];
                    float d = xi0.x*b0.x + xi0.y*b0.y + xi0.z*b0.z + xi0.w*b0.w
                            + xi1.x*b1.x + xi1.y*b1.y + xi1.z*b1.z + xi1.w*b1.w
                            + xi2.x*b2.x + xi2.y*b2.y + xi2.z*b2.z + xi2.w*b2.w
                            + xi3.x*b3.x + xi3.y*b3.y + xi3.z*b3.z + xi3.w*b3.w;
                    #pragma unroll
                    for (int o = 16; o > 0; o >>= 1)
                        d += __shfl_down_sync(0xffffffffu, d, o);
                    if (lane == 0 && (jt + rr) != i) {
                        float e = expf(d / TEMP);
                        sum += e;
                        if (jlab[rr] == labi) pos += e;
                    }
                }
            }
        }
        if (active && lane == 0) {
            atomicAdd(&g_sum[i], sum);
            atomicAdd(&g_pos[i], pos);
        }
    }

    // ================= arrive + finalize (all blocks) =================
    __threadfence();
    __syncthreads();
    if (tid == 0) {
        int old = atomicAdd(&g_done, 1);
        sdone = (old == (int)(gridDim.x * gridDim.y) - 1) ? 1 : 0;
    }
    __syncthreads();
    if (sdone) {
        float l = 0.f;
        for (int q = tid; q < S; q += 256)
            l += -logf(g_pos[q] / g_sum[q]);
        #pragma unroll
        for (int o = 16; o > 0; o >>= 1) l += __shfl_down_sync(0xffffffffu, l, o);
        if (lane == 0) wred[wid] = l;
        __syncthreads();
        if (tid == 0) {
            float usum = 0.f;
            #pragma unroll
            for (int w = 0; w < 8; w++) usum += wred[w];
            size_t ND = (size_t)N * D;
            out[ND]     = 1.25f * g_loss / (float)((size_t)N * D);
            out[ND + 1] = usum / (float)S;
            g_done = 0;
        }
    }
}

// ---------------- launcher ----------------
extern "C" void kernel_launch(void* const* d_in, const int* in_sizes, int n_in,
                              void* d_out, int out_size) {
    const float* x       = (const float*)d_in[0];
    const int*   Q       = (const int*)d_in[1];
    const float* emb     = (const float*)d_in[2];
    const int*   sampled = (const int*)d_in[3];
    float* out = (float*)d_out;

    int N = in_sizes[0] / D;
    int S = in_sizes[3];
    size_t ND = (size_t)N * D;
    float* out_idx = out + ND + 2;

    cudaFuncSetAttribute(k_fused, cudaFuncAttributeMaxDynamicSharedMemorySize,
                         8 * STW * 4);

    k_prep<<<NCODES + HB + S, 128>>>(emb, Q, N, sampled, S);
    k_scatter<<<(N + 255) / 256, 256>>>(Q, N);
    int usim_rows = (S + 7) / 8;
    dim3 gg(MAXTILES, NTYPES + usim_rows);
    k_fused<<<gg, 256, 8 * STW * 4>>>(x, emb, out, out_idx, sampled, S, N);
}